// round 4
// baseline (speedup 1.0000x reference)
#include <cuda_runtime.h>
#include <cstdint>

#define NCL     16
#define CSZ     8
#define NBLK    (NCL*CSZ)
#define NTHR    256
#define HD      256
#define DIM     3
#define LT      20
#define NCLASS  10
#define NSTEPS  380
#define ROWS    32
#define WST     260      // weight row stride (floats)
#define AST     260      // activation column stride (floats) -> bank rotation by 4
#define BPC     16

// ---- smem layout (float-word offsets) ----
#define OFF_W    0                       // [5][ROWS][WST] = 41600
#define OFF_B    (5*ROWS*WST)            // [5][ROWS] = 160
#define OFF_T    (OFF_B + 5*ROWS)        // [LT] -> 32
#define OFF_MB   (OFF_T + 32)            // 8 mbarriers (u64) = 16 words (byte off 8-aligned)
#define NMB      8
#define OFF_Z    (OFF_MB + 16)           // [16][AST] col-major z
#define OFF_H0   (OFF_Z  + BPC*AST)
#define OFF_H1   (OFF_H0 + BPC*AST)
#define OFF_STG  (OFF_H1 + BPC*AST)      // 8 slots x [8 cols][32 rows] = 2048
#define SMEM_WORDS (OFF_STG + 8*256)
#define SMEM_BYTES (SMEM_WORDS*4)        // 225,344 B  (< 227KB cap)

#define MBI(l,g) ((l)*2+(g))             // l: 0=h0(L1) 1=h1(L2) 2=h0'(L3) 3=z(L4)
#define TXB 8192u                         // bytes per barrier phase: 256*8*4

// ---------------- helpers ----------------
__device__ __forceinline__ float2 ffma2(float2 a, float2 b, float2 c) {
    float2 d;
    asm("fma.rn.f32x2 %0, %1, %2, %3;"
        : "=l"(*(unsigned long long*)&d)
        : "l"(*(unsigned long long*)&a),
          "l"(*(unsigned long long*)&b),
          "l"(*(unsigned long long*)&c));
    return d;
}
__device__ __forceinline__ float lipswish(float x) {
    return 0.909f * x / (1.0f + __expf(-x));
}
__device__ __forceinline__ uint32_t smem_u32(const void* p) {
    uint32_t a;
    asm("{ .reg .u64 t; cvta.to.shared.u64 t, %1; cvt.u32.u64 %0, t; }" : "=r"(a) : "l"(p));
    return a;
}
__device__ __forceinline__ uint32_t mapa_u32(uint32_t a, uint32_t rank) {
    uint32_t d;
    asm("mapa.shared::cluster.u32 %0, %1, %2;" : "=r"(d) : "r"(a), "r"(rank));
    return d;
}
__device__ __forceinline__ void cluster_bar() {
    asm volatile("barrier.cluster.arrive.aligned;" ::: "memory");
    asm volatile("barrier.cluster.wait.aligned;"   ::: "memory");
}
__device__ __forceinline__ void mb_init(uint32_t mb, uint32_t cnt) {
    asm volatile("mbarrier.init.shared.b64 [%0], %1;" :: "r"(mb), "r"(cnt) : "memory");
}
__device__ __forceinline__ void mb_arm(uint32_t mb, uint32_t tx) {
    asm volatile("mbarrier.arrive.expect_tx.shared.b64 _, [%0], %1;" :: "r"(mb), "r"(tx) : "memory");
}
__device__ __forceinline__ void mb_wait(uint32_t mb, uint32_t parity) {
    uint32_t done;
    asm volatile(
        "{\n\t.reg .pred p;\n\t"
        "mbarrier.try_wait.parity.acquire.cta.shared::cta.b64 p, [%1], %2, 0x989680;\n\t"
        "selp.b32 %0, 1, 0, p;\n\t}"
        : "=r"(done) : "r"(mb), "r"(parity) : "memory");
    while (!done) {
        asm volatile(
            "{\n\t.reg .pred p;\n\t"
            "mbarrier.try_wait.parity.acquire.cta.shared::cta.b64 p, [%1], %2, 0x989680;\n\t"
            "selp.b32 %0, 1, 0, p;\n\t}"
            : "=r"(done) : "r"(mb), "r"(parity) : "memory");
    }
}

// one 128B bulk copy per (col, dest): staging[slot][cg][32] -> peer buf[c][rank*32..]
__device__ __forceinline__ void send_group(const uint32_t* __restrict__ pb, uint32_t smb,
                                           int slot, int dstw, int group, int mbi,
                                           int tid, uint32_t rank) {
    if (tid < 64) {
        int cg  = tid & 7;
        int dst = tid >> 3;
        int c   = group * 8 + cg;
        uint32_t src = smb + (uint32_t)(OFF_STG + slot*256 + cg*32) * 4u;
        uint32_t d   = pb[dst] + (uint32_t)(dstw + c*AST + (int)rank*ROWS) * 4u;
        uint32_t mb  = pb[dst] + (uint32_t)(OFF_MB*4 + mbi*8);
        asm volatile("fence.proxy.async.shared::cta;" ::: "memory");
        asm volatile(
            "cp.async.bulk.shared::cluster.shared::cta.mbarrier::complete_tx::bytes "
            "[%0], [%1], %2, [%3];"
            :: "r"(d), "r"(src), "r"(128u), "r"(mb) : "memory");
    }
}

// 256-K dot: weight row (contiguous float4) vs activation column (contiguous float4)
__device__ __forceinline__ float dotc64(const float4* __restrict__ w,
                                        const float4* __restrict__ a) {
    float2 s0 = make_float2(0.f, 0.f), s1 = make_float2(0.f, 0.f);
#pragma unroll 16
    for (int k = 0; k < 64; k++) {
        float4 wv = w[k];
        float4 av = a[k];
        s0 = ffma2(make_float2(wv.x, wv.y), make_float2(av.x, av.y), s0);
        s1 = ffma2(make_float2(wv.z, wv.w), make_float2(av.z, av.w), s1);
    }
    return (s0.x + s0.y) + (s1.x + s1.y);
}

// ---------------- kernel ----------------
__global__ void __launch_bounds__(NTHR, 1)
ncde_kernel(const float* __restrict__ coeffs, const float* __restrict__ times_g,
            const float* __restrict__ W_init, const float* __restrict__ b_init,
            const float* __restrict__ W_in,   const float* __restrict__ b_in,
            const float* __restrict__ W_hh,   const float* __restrict__ b_hh,
            const float* __restrict__ W_out,  const float* __restrict__ b_out,
            const float* __restrict__ Wc1,    const float* __restrict__ bc1,
            const float* __restrict__ Wc2,    const float* __restrict__ bc2,
            float* __restrict__ out) {
    extern __shared__ float sm[];
    const int tid = threadIdx.x;
    const int cl  = blockIdx.x / CSZ;
    unsigned rank;
    asm("mov.u32 %0, %%cluster_ctarank;" : "=r"(rank));
    const int r  = tid >> 3;          // 0..31 local row
    const int c  = tid & 7;           // 0..7 col-in-group
    const int cA = c, cB = c + 8;

    const uint32_t smb = smem_u32(sm);
    uint32_t pb[CSZ];
#pragma unroll
    for (int rr = 0; rr < CSZ; rr++) pb[rr] = mapa_u32(smb, rr);
#define MBA(i) (smb + OFF_MB*4 + (i)*8)

    // ---- preload weights (zero-padded), biases, times ----
    {
        const float* srcs[5] = {W_in, W_hh, W_hh + HD*HD, W_out, Wc1};
        const int    kw[5]   = {HD + DIM, HD, HD, HD, HD};
#pragma unroll
        for (int m = 0; m < 5; m++) {
            const float* s = srcs[m];
            const int K = kw[m];
            float* wd = sm + OFF_W + m*ROWS*WST;
            for (int idx = tid; idx < ROWS*WST; idx += NTHR) {
                int rr2 = idx / WST, k = idx % WST;
                wd[idx] = (k < K) ? s[((int)rank*ROWS + rr2)*K + k] : 0.0f;
            }
        }
        const float* bs[5] = {b_in, b_hh, b_hh + HD, b_out, bc1};
        if (tid < ROWS)
#pragma unroll
            for (int m = 0; m < 5; m++)
                sm[OFF_B + m*ROWS + tid] = bs[m][(int)rank*ROWS + tid];
        if (tid < LT) sm[OFF_T + tid] = times_g[tid];
    }
    if (tid == 0) {
#pragma unroll
        for (int i = 0; i < NMB; i++) { mb_init(MBA(i), 1); mb_arm(MBA(i), TXB); }
    }
    __syncthreads();
    cluster_bar();   // all barriers live before any bulk copy

    const float t0 = sm[OFF_T];
    const float dt = (sm[OFF_T + LT - 1] - t0) / (float)NSTEPS;
    float t = t0;

    // xt(t) for one batch column, in registers
    auto eval_x = [&](int col, float tt) -> float3 {
        int idx = 0;
#pragma unroll
        for (int i = 1; i <= LT - 2; i++) idx = (sm[OFF_T + i] <= tt) ? i : idx;
        float ta = sm[OFF_T + idx], tb = sm[OFF_T + idx + 1];
        float w = (tt - ta) / (tb - ta), om = 1.0f - w;
        const float* c0 = coeffs + ((cl*BPC + col)*LT + idx)*DIM;
        float3 x;
        x.x = c0[0]*om + c0[DIM+0]*w;
        x.y = c0[1]*om + c0[DIM+1]*w;
        x.z = c0[2]*om + c0[DIM+2]*w;
        return x;
    };

    // ---- z0 = W_init @ x(t0) + b_init, full [16][256] locally in every CTA ----
    if (tid < BPC) {
        float3 x = eval_x(tid, t);
        sm[OFF_STG + tid*4 + 0] = x.x;
        sm[OFF_STG + tid*4 + 1] = x.y;
        sm[OFF_STG + tid*4 + 2] = x.z;
    }
    __syncthreads();
    for (int i = 0; i < (HD*BPC)/NTHR; i++) {
        int idx = i*NTHR + tid;
        int col = idx & 15, row = idx >> 4;
        const float* xv = sm + OFF_STG + col*4;
        float v = b_init[row]
                + W_init[row*DIM+0]*xv[0]
                + W_init[row*DIM+1]*xv[1]
                + W_init[row*DIM+2]*xv[2];
        sm[OFF_Z + col*AST + row] = v;
    }
    __syncthreads();

    const bool lead = (tid == 0);
    const float* w0r = sm + OFF_W + 0*ROWS*WST + r*WST;
    const float4* wm0 = (const float4*)w0r;
    const float4* wm1 = (const float4*)(sm + OFF_W + 1*ROWS*WST + r*WST);
    const float4* wm2 = (const float4*)(sm + OFF_W + 2*ROWS*WST + r*WST);
    const float4* wm3 = (const float4*)(sm + OFF_W + 3*ROWS*WST + r*WST);
    const float bi0 = sm[OFF_B + 0*ROWS + r];
    const float bi1 = sm[OFF_B + 1*ROWS + r];
    const float bi2 = sm[OFF_B + 2*ROWS + r];
    const float bi3 = sm[OFF_B + 3*ROWS + r];
    const float wt0 = w0r[256], wt1 = w0r[257], wt2 = w0r[258];
    float* stg = sm + OFF_STG;

    // ---- main Euler loop ----
    for (int s = 0; s < NSTEPS; s++) {
        const uint32_t ph = (uint32_t)(s & 1);
        const uint32_t pz = ph ^ 1u;

        // L1 group A
        if (s) { mb_wait(MBA(MBI(3,0)), pz); if (lead) mb_arm(MBA(MBI(3,0)), TXB); }
        {
            float3 x = eval_x(cA, t);
            float v = dotc64(wm0, (const float4*)(sm + OFF_Z + cA*AST));
            v += wt0*x.x + wt1*x.y + wt2*x.z;
            stg[0*256 + c*32 + r] = lipswish(v + bi0);
        }
        __syncthreads();
        send_group(pb, smb, 0, OFF_H0, 0, MBI(0,0), tid, rank);
        // L1 group B
        if (s) { mb_wait(MBA(MBI(3,1)), pz); if (lead) mb_arm(MBA(MBI(3,1)), TXB); }
        {
            float3 x = eval_x(cB, t);
            float v = dotc64(wm0, (const float4*)(sm + OFF_Z + cB*AST));
            v += wt0*x.x + wt1*x.y + wt2*x.z;
            stg[1*256 + c*32 + r] = lipswish(v + bi0);
        }
        __syncthreads();
        send_group(pb, smb, 1, OFF_H0, 1, MBI(0,1), tid, rank);

        // L2
        mb_wait(MBA(MBI(0,0)), ph); if (lead) mb_arm(MBA(MBI(0,0)), TXB);
        stg[2*256 + c*32 + r] = lipswish(dotc64(wm1, (const float4*)(sm + OFF_H0 + cA*AST)) + bi1);
        __syncthreads();
        send_group(pb, smb, 2, OFF_H1, 0, MBI(1,0), tid, rank);
        mb_wait(MBA(MBI(0,1)), ph); if (lead) mb_arm(MBA(MBI(0,1)), TXB);
        stg[3*256 + c*32 + r] = lipswish(dotc64(wm1, (const float4*)(sm + OFF_H0 + cB*AST)) + bi1);
        __syncthreads();
        send_group(pb, smb, 3, OFF_H1, 1, MBI(1,1), tid, rank);

        // L3 (writes H0 again; safe via barrier chain)
        mb_wait(MBA(MBI(1,0)), ph); if (lead) mb_arm(MBA(MBI(1,0)), TXB);
        stg[4*256 + c*32 + r] = lipswish(dotc64(wm2, (const float4*)(sm + OFF_H1 + cA*AST)) + bi2);
        __syncthreads();
        send_group(pb, smb, 4, OFF_H0, 0, MBI(2,0), tid, rank);
        mb_wait(MBA(MBI(1,1)), ph); if (lead) mb_arm(MBA(MBI(1,1)), TXB);
        stg[5*256 + c*32 + r] = lipswish(dotc64(wm2, (const float4*)(sm + OFF_H1 + cB*AST)) + bi2);
        __syncthreads();
        send_group(pb, smb, 5, OFF_H0, 1, MBI(2,1), tid, rank);

        // L4: z <- z + dt * tanh(W_out @ h)
        mb_wait(MBA(MBI(2,0)), ph); if (lead) mb_arm(MBA(MBI(2,0)), TXB);
        {
            float f  = tanhf(dotc64(wm3, (const float4*)(sm + OFF_H0 + cA*AST)) + bi3);
            float zo = sm[OFF_Z + cA*AST + (int)rank*ROWS + r];
            stg[6*256 + c*32 + r] = fmaf(dt, f, zo);
        }
        __syncthreads();
        send_group(pb, smb, 6, OFF_Z, 0, MBI(3,0), tid, rank);
        mb_wait(MBA(MBI(2,1)), ph); if (lead) mb_arm(MBA(MBI(2,1)), TXB);
        {
            float f  = tanhf(dotc64(wm3, (const float4*)(sm + OFF_H0 + cB*AST)) + bi3);
            float zo = sm[OFF_Z + cB*AST + (int)rank*ROWS + r];
            stg[7*256 + c*32 + r] = fmaf(dt, f, zo);
        }
        __syncthreads();
        send_group(pb, smb, 7, OFF_Z, 1, MBI(3,1), tid, rank);

        t = t + dt;
    }

    // ---- final z arrivals (last sends at s=379 -> parity 1) ----
    mb_wait(MBA(MBI(3,0)), 1u);
    mb_wait(MBA(MBI(3,1)), 1u);

    // ---- classifier hidden: relu(Wc1 @ z + bc1) -> H1 (parity 0) ----
    {
        const float4* wm4 = (const float4*)(sm + OFF_W + 4*ROWS*WST + r*WST);
        const float bi4 = sm[OFF_B + 4*ROWS + r];
        stg[0*256 + c*32 + r] = fmaxf(dotc64(wm4, (const float4*)(sm + OFF_Z + cA*AST)) + bi4, 0.0f);
        __syncthreads();
        send_group(pb, smb, 0, OFF_H1, 0, MBI(1,0), tid, rank);
        stg[1*256 + c*32 + r] = fmaxf(dotc64(wm4, (const float4*)(sm + OFF_Z + cB*AST)) + bi4, 0.0f);
        __syncthreads();
        send_group(pb, smb, 1, OFF_H1, 1, MBI(1,1), tid, rank);
    }
    mb_wait(MBA(MBI(1,0)), 0u);
    mb_wait(MBA(MBI(1,1)), 0u);

    // ---- output: out = Wc2 @ h + bc2 (rank 0 only) ----
    if (rank == 0 && tid < BPC*NCLASS) {
        int b = tid / NCLASS, cls = tid % NCLASS;
        const float4* hv = (const float4*)(sm + OFF_H1 + b*AST);
        const float4* wv = (const float4*)(Wc2 + cls*HD);
        float2 s0 = make_float2(0.f, 0.f), s1 = make_float2(0.f, 0.f);
#pragma unroll 16
        for (int k = 0; k < 64; k++) {
            float4 w = wv[k], h = hv[k];
            s0 = ffma2(make_float2(w.x, w.y), make_float2(h.x, h.y), s0);
            s1 = ffma2(make_float2(w.z, w.w), make_float2(h.z, h.w), s1);
        }
        out[(cl*BPC + b)*NCLASS + cls] = bc2[cls] + (s0.x + s0.y) + (s1.x + s1.y);
    }

    cluster_bar();   // no CTA exits while peers may still write its smem
}

// ---------------- launch ----------------
extern "C" void kernel_launch(void* const* d_in, const int* in_sizes, int n_in,
                              void* d_out, int out_size) {
    (void)in_sizes; (void)n_in; (void)out_size;
    cudaFuncSetAttribute(ncde_kernel, cudaFuncAttributeMaxDynamicSharedMemorySize, SMEM_BYTES);

    cudaLaunchConfig_t cfg = {};
    cfg.gridDim  = dim3(NBLK, 1, 1);
    cfg.blockDim = dim3(NTHR, 1, 1);
    cfg.dynamicSmemBytes = SMEM_BYTES;
    cfg.stream = 0;

    cudaLaunchAttribute attrs[1];
    attrs[0].id = cudaLaunchAttributeClusterDimension;
    attrs[0].val.clusterDim.x = CSZ;
    attrs[0].val.clusterDim.y = 1;
    attrs[0].val.clusterDim.z = 1;
    cfg.attrs = attrs;
    cfg.numAttrs = 1;

    cudaLaunchKernelEx(&cfg, ncde_kernel,
        (const float*)d_in[0],  (const float*)d_in[1],
        (const float*)d_in[2],  (const float*)d_in[3],
        (const float*)d_in[4],  (const float*)d_in[5],
        (const float*)d_in[6],  (const float*)d_in[7],
        (const float*)d_in[8],  (const float*)d_in[9],
        (const float*)d_in[10], (const float*)d_in[11],
        (const float*)d_in[12], (const float*)d_in[13],
        (float*)d_out);
}

// round 6
// speedup vs baseline: 1.0818x; 1.0818x over previous
#include <cuda_runtime.h>
#include <cstdint>

#define NCLU    8          // clusters
#define CSZ     8          // CTAs per cluster
#define NBLK    (NCLU*CSZ) // 64 CTAs
#define NTHR    256
#define BPC     32         // batch cols per cluster
#define NG      4          // independent column groups (chains) of 8 cols
#define HD      256
#define DIM     3
#define LT      20
#define NCLASS  10
#define NSTEPS  380
#define ROWS    32
#define WST     260        // padded weight row stride (floats)

// ---- smem word offsets ----
#define OFF_W   0                    // [4][ROWS][WST] = 33280
#define OFF_B   (4*ROWS*WST)         // [4][ROWS] = 128
#define OFF_T   (OFF_B + 4*ROWS)     // [20]
#define OFF_MB  (OFF_T + 20)         // 33428 (even word -> 8B aligned), 16 mbarriers
#define OFF_Z   (OFF_MB + 32)        // [32 cols][256] XOR-swizzled float4 slots
#define OFF_H0  (OFF_Z  + BPC*HD)
#define OFF_H1  (OFF_H0 + BPC*HD)
#define SMEM_WORDS (OFF_H1 + BPC*HD) // 58036
#define SMEM_BYTES (SMEM_WORDS*4)    // 232144 <= 232448 cap

#define MBI(l,g) ((l)*NG+(g))        // l: 0=H0(L1) 1=H1(L2) 2=H0(L3) 3=Z(L4)
#define TXB 8192u                    // 256 rows * 8 cols * 4B per phase

// ---------------- helpers ----------------
__device__ __forceinline__ float2 ffma2(float2 a, float2 b, float2 c) {
    float2 d;
    asm("fma.rn.f32x2 %0, %1, %2, %3;"
        : "=l"(*(unsigned long long*)&d)
        : "l"(*(unsigned long long*)&a),
          "l"(*(unsigned long long*)&b),
          "l"(*(unsigned long long*)&c));
    return d;
}
__device__ __forceinline__ float lipswish(float x) {
    return 0.909f * x / (1.0f + __expf(-x));
}
__device__ __forceinline__ uint32_t smem_u32(const void* p) {
    uint32_t a;
    asm("{ .reg .u64 t; cvta.to.shared.u64 t, %1; cvt.u32.u64 %0, t; }" : "=r"(a) : "l"(p));
    return a;
}
__device__ __forceinline__ uint32_t mapa_u32(uint32_t a, uint32_t rank) {
    uint32_t d;
    asm("mapa.shared::cluster.u32 %0, %1, %2;" : "=r"(d) : "r"(a), "r"(rank));
    return d;
}
__device__ __forceinline__ void cluster_bar() {
    asm volatile("barrier.cluster.arrive.aligned;" ::: "memory");
    asm volatile("barrier.cluster.wait.aligned;"   ::: "memory");
}
__device__ __forceinline__ void mb_init(uint32_t mb, uint32_t cnt) {
    asm volatile("mbarrier.init.shared.b64 [%0], %1;" :: "r"(mb), "r"(cnt) : "memory");
}
__device__ __forceinline__ void mb_arm(uint32_t mb, uint32_t tx) {
    asm volatile("mbarrier.arrive.expect_tx.shared.b64 _, [%0], %1;" :: "r"(mb), "r"(tx) : "memory");
}
__device__ __forceinline__ void mb_wait(uint32_t mb, uint32_t parity) {
    uint32_t done;
    asm volatile(
        "{\n\t.reg .pred p;\n\t"
        "mbarrier.try_wait.parity.acquire.cta.shared::cta.b64 p, [%1], %2, 0x989680;\n\t"
        "selp.b32 %0, 1, 0, p;\n\t}"
        : "=r"(done) : "r"(mb), "r"(parity) : "memory");
    while (!done) {
        asm volatile(
            "{\n\t.reg .pred p;\n\t"
            "mbarrier.try_wait.parity.acquire.cta.shared::cta.b64 p, [%1], %2, 0x989680;\n\t"
            "selp.b32 %0, 1, 0, p;\n\t}"
            : "=r"(done) : "r"(mb), "r"(parity) : "memory");
    }
}
// send one value to the same swizzled slot in all 8 CTAs' smem, feeding barrier mbi
__device__ __forceinline__ void scatter(const uint32_t* __restrict__ pb,
                                        int mbi, uint32_t word_off, float v) {
    uint32_t eoff = word_off * 4u;
    uint32_t moff = (uint32_t)(OFF_MB + mbi * 2) * 4u;
#pragma unroll
    for (int rr = 0; rr < CSZ; rr++) {
        asm volatile(
            "st.async.weak.shared::cluster.mbarrier::complete_tx::bytes.b32 [%0], %1, [%2];"
            :: "r"(pb[rr] + eoff), "f"(v), "r"(pb[rr] + moff) : "memory");
    }
}
// dot: padded weight row (linear float4) vs one swizzled activation COLUMN
// acol must point at the column base (includes cb*HD); slot k is stored at k^sc.
__device__ __forceinline__ float dot_swz(const float* __restrict__ wrow,
                                         const float* __restrict__ acol, int sc) {
    const float4* w4 = (const float4*)wrow;
    const float4* a4 = (const float4*)acol;
    float2 s0 = make_float2(0.f, 0.f), s1 = make_float2(0.f, 0.f);
#pragma unroll
    for (int k = 0; k < 64; k++) {
        float4 wv = w4[k];
        float4 av = a4[k ^ sc];
        s0 = ffma2(make_float2(wv.x, wv.y), make_float2(av.x, av.y), s0);
        s1 = ffma2(make_float2(wv.z, wv.w), make_float2(av.z, av.w), s1);
    }
    return (s0.x + s0.y) + (s1.x + s1.y);
}

// ---------------- kernel ----------------
__global__ void __launch_bounds__(NTHR, 1)
ncde_kernel(const float* __restrict__ coeffs, const float* __restrict__ times_g,
            const float* __restrict__ W_init, const float* __restrict__ b_init,
            const float* __restrict__ W_in,   const float* __restrict__ b_in,
            const float* __restrict__ W_hh,   const float* __restrict__ b_hh,
            const float* __restrict__ W_out,  const float* __restrict__ b_out,
            const float* __restrict__ Wc1,    const float* __restrict__ bc1,
            const float* __restrict__ Wc2,    const float* __restrict__ bc2,
            float* __restrict__ out) {
    extern __shared__ float sm[];
    const int tid = threadIdx.x;
    const int cl  = blockIdx.x / CSZ;
    unsigned rank;
    asm("mov.u32 %0, %%cluster_ctarank;" : "=r"(rank));
    const int r   = tid >> 3;            // 0..31 local row
    const int cb  = tid & 7;             // col within group (also the swizzle key)
    const int R   = (int)rank * ROWS + r;
    // per-thread swizzled in-column word offset for (R, col with col&7==cb)
    const uint32_t swzR = (uint32_t)((((R >> 2) ^ cb) << 2) + (R & 3));
    const uint32_t colw = (uint32_t)(cb * HD) + swzR;   // + g*2048 + buffer base
    const int colbase = cb * HD;                        // column base for reads

    const uint32_t smb = smem_u32(sm);
    uint32_t pb[CSZ];
#pragma unroll
    for (int rr = 0; rr < CSZ; rr++) pb[rr] = mapa_u32(smb, rr);
#define MBA(i) (smb + (OFF_MB + (i)*2)*4)

    // ---- preload weights (4 in-loop matrices), biases, times ----
    {
        const float* srcs[4] = {W_in, W_hh, W_hh + HD*HD, W_out};
        const int    kw[4]   = {HD + DIM, HD, HD, HD};
#pragma unroll
        for (int m = 0; m < 4; m++) {
            const float* s = srcs[m];
            const int K = kw[m];
            float* wd = sm + OFF_W + m*ROWS*WST;
            for (int idx = tid; idx < ROWS*WST; idx += NTHR) {
                int rr2 = idx / WST, k = idx % WST;
                wd[idx] = (k < K) ? s[((int)rank*ROWS + rr2)*K + k] : 0.0f;
            }
        }
        const float* bs[4] = {b_in, b_hh, b_hh + HD, b_out};
        if (tid < ROWS)
#pragma unroll
            for (int m = 0; m < 4; m++)
                sm[OFF_B + m*ROWS + tid] = bs[m][(int)rank*ROWS + tid];
        if (tid < LT) sm[OFF_T + tid] = times_g[tid];
    }
    if (tid == 0) {
#pragma unroll
        for (int i = 0; i < 16; i++) { mb_init(MBA(i), 1); mb_arm(MBA(i), TXB); }
    }
    __syncthreads();
    cluster_bar();     // all barriers live before any st.async

    const float t0 = sm[OFF_T];
    const float dt = (sm[OFF_T + LT - 1] - t0) / (float)NSTEPS;
    float t = t0;

    auto eval_x = [&](int col, float tt) -> float3 {
        int idx = 0;
#pragma unroll
        for (int i = 1; i <= LT - 2; i++) idx = (sm[OFF_T + i] <= tt) ? i : idx;
        float ta = sm[OFF_T + idx], tb = sm[OFF_T + idx + 1];
        float w = (tt - ta) / (tb - ta), om = 1.0f - w;
        const float* c0 = coeffs + ((cl*BPC + col)*LT + idx)*DIM;
        float3 x;
        x.x = c0[0]*om + c0[DIM+0]*w;
        x.y = c0[1]*om + c0[DIM+1]*w;
        x.z = c0[2]*om + c0[DIM+2]*w;
        return x;
    };

    // ---- z0 = W_init @ x(t0) + b_init, full [32][256] locally (x scratch in H1) ----
    if (tid < BPC) {
        float3 x = eval_x(tid, t);
        sm[OFF_H1 + tid*4 + 0] = x.x;
        sm[OFF_H1 + tid*4 + 1] = x.y;
        sm[OFF_H1 + tid*4 + 2] = x.z;
    }
    __syncthreads();
    {
        const int row = tid;
        const float wa = W_init[row*DIM+0], wb = W_init[row*DIM+1], wc = W_init[row*DIM+2];
        const float bb = b_init[row];
        const uint32_t rsl = (uint32_t)(row & 3);
        const uint32_t rtp = (uint32_t)(row >> 2);
#pragma unroll 4
        for (int col = 0; col < BPC; col++) {
            const float* xv = sm + OFF_H1 + col*4;
            float v = bb + wa*xv[0] + wb*xv[1] + wc*xv[2];
            sm[OFF_Z + col*HD + (((rtp ^ (uint32_t)(col & 7)) << 2) + rsl)] = v;
        }
    }
    __syncthreads();

    const bool lead = (tid == 0);
    const float* w0r = sm + OFF_W + 0*ROWS*WST + r*WST;
    const float* w1r = sm + OFF_W + 1*ROWS*WST + r*WST;
    const float* w2r = sm + OFF_W + 2*ROWS*WST + r*WST;
    const float* w3r = sm + OFF_W + 3*ROWS*WST + r*WST;
    const float bi0 = sm[OFF_B + 0*ROWS + r];
    const float bi1 = sm[OFF_B + 1*ROWS + r];
    const float bi2 = sm[OFF_B + 2*ROWS + r];
    const float bi3 = sm[OFF_B + 3*ROWS + r];
    const float wt0 = w0r[256], wt1 = w0r[257], wt2 = w0r[258];

    // ---- main Euler loop: 4 independent chains, zero __syncthreads ----
    for (int s = 0; s < NSTEPS; s++) {
        const uint32_t ph = (uint32_t)(s & 1);
        const uint32_t pz = ph ^ 1u;

        // L1: lipswish(W_in @ [z;x]) -> H0, barriers 0..3
#pragma unroll
        for (int g = 0; g < NG; g++) {
            if (s) { mb_wait(MBA(MBI(3,g)), pz); if (lead) mb_arm(MBA(MBI(3,g)), TXB); }
            float3 x = eval_x(g*8 + cb, t);
            float v = dot_swz(w0r, sm + OFF_Z + g*8*HD + colbase, cb);
            v = lipswish(v + wt0*x.x + wt1*x.y + wt2*x.z + bi0);
            scatter(pb, MBI(0,g), (uint32_t)(OFF_H0 + g*8*HD) + colw, v);
        }
        // L2 -> H1, barriers 4..7
#pragma unroll
        for (int g = 0; g < NG; g++) {
            mb_wait(MBA(MBI(0,g)), ph); if (lead) mb_arm(MBA(MBI(0,g)), TXB);
            float v = lipswish(dot_swz(w1r, sm + OFF_H0 + g*8*HD + colbase, cb) + bi1);
            scatter(pb, MBI(1,g), (uint32_t)(OFF_H1 + g*8*HD) + colw, v);
        }
        // L3 -> H0, barriers 8..11
#pragma unroll
        for (int g = 0; g < NG; g++) {
            mb_wait(MBA(MBI(1,g)), ph); if (lead) mb_arm(MBA(MBI(1,g)), TXB);
            float v = lipswish(dot_swz(w2r, sm + OFF_H1 + g*8*HD + colbase, cb) + bi2);
            scatter(pb, MBI(2,g), (uint32_t)(OFF_H0 + g*8*HD) + colw, v);
        }
        // L4: z += dt*tanh(W_out @ h) -> Z, barriers 12..15
#pragma unroll
        for (int g = 0; g < NG; g++) {
            mb_wait(MBA(MBI(2,g)), ph); if (lead) mb_arm(MBA(MBI(2,g)), TXB);
            float f  = tanhf(dot_swz(w3r, sm + OFF_H0 + g*8*HD + colbase, cb) + bi3);
            float zo = sm[OFF_Z + g*8*HD + (int)colw];
            scatter(pb, MBI(3,g), (uint32_t)(OFF_Z + g*8*HD) + colw, fmaf(dt, f, zo));
        }
        t = t + dt;
    }

    // ---- final z (step 379 -> parity 1) ----
#pragma unroll
    for (int g = 0; g < NG; g++) mb_wait(MBA(MBI(3,g)), 1u);

    // ---- classifier hidden: relu(Wc1 @ z + bc1) -> H0, barriers 0..3 parity 0 ----
    {
        const float4* wg = (const float4*)(Wc1 + R*HD);
        const float bi4 = bc1[R];
#pragma unroll
        for (int g = 0; g < NG; g++) {
            const float4* a4 = (const float4*)(sm + OFF_Z + g*8*HD + colbase);
            float2 s0 = make_float2(0.f, 0.f), s1 = make_float2(0.f, 0.f);
#pragma unroll 16
            for (int k = 0; k < 64; k++) {
                float4 wv = __ldg(wg + k);
                float4 av = a4[k ^ cb];
                s0 = ffma2(make_float2(wv.x, wv.y), make_float2(av.x, av.y), s0);
                s1 = ffma2(make_float2(wv.z, wv.w), make_float2(av.z, av.w), s1);
            }
            float v = fmaxf((s0.x + s0.y) + (s1.x + s1.y) + bi4, 0.0f);
            scatter(pb, MBI(0,g), (uint32_t)(OFF_H0 + g*8*HD) + colw, v);
        }
#pragma unroll
        for (int g = 0; g < NG; g++) mb_wait(MBA(MBI(0,g)), 0u);
    }

    // ---- out = Wc2 @ h + bc2 (rank 0; 320 items) ----
    if (rank == 0) {
        for (int item = tid; item < BPC*NCLASS; item += NTHR) {
            int b = item / NCLASS, cls = item % NCLASS;
            int sb = b & 7;
            const float* hb = sm + OFF_H0 + b*HD;
            const float* wr = Wc2 + cls*HD;
            float acc = bc2[cls];
#pragma unroll 8
            for (int k = 0; k < HD; k++) {
                float hv = hb[(((k >> 2) ^ sb) << 2) + (k & 3)];
                acc = fmaf(hv, wr[k], acc);
            }
            out[(cl*BPC + b)*NCLASS + cls] = acc;
        }
    }

    cluster_bar();   // no CTA exits while peers may still write its smem
}

// ---------------- launch ----------------
extern "C" void kernel_launch(void* const* d_in, const int* in_sizes, int n_in,
                              void* d_out, int out_size) {
    (void)in_sizes; (void)n_in; (void)out_size;
    cudaFuncSetAttribute(ncde_kernel, cudaFuncAttributeMaxDynamicSharedMemorySize, SMEM_BYTES);

    cudaLaunchConfig_t cfg = {};
    cfg.gridDim  = dim3(NBLK, 1, 1);
    cfg.blockDim = dim3(NTHR, 1, 1);
    cfg.dynamicSmemBytes = SMEM_BYTES;
    cfg.stream = 0;

    cudaLaunchAttribute attrs[1];
    attrs[0].id = cudaLaunchAttributeClusterDimension;
    attrs[0].val.clusterDim.x = CSZ;
    attrs[0].val.clusterDim.y = 1;
    attrs[0].val.clusterDim.z = 1;
    cfg.attrs = attrs;
    cfg.numAttrs = 1;

    cudaLaunchKernelEx(&cfg, ncde_kernel,
        (const float*)d_in[0],  (const float*)d_in[1],
        (const float*)d_in[2],  (const float*)d_in[3],
        (const float*)d_in[4],  (const float*)d_in[5],
        (const float*)d_in[6],  (const float*)d_in[7],
        (const float*)d_in[8],  (const float*)d_in[9],
        (const float*)d_in[10], (const float*)d_in[11],
        (const float*)d_in[12], (const float*)d_in[13],
        (float*)d_out);
}